// round 1
// baseline (speedup 1.0000x reference)
#include <cuda_runtime.h>
#include <math.h>

// Problem constants
#define Bc   16
#define Hc   48
#define Wc   48
#define WSc  6
#define NHc  16
#define DIMc 512
#define HEADc 32
#define Lc   2304          // 48*48
#define Mc   36            // WS*WS
#define NWc  64            // (48/6)^2
#define HID  2048          // 4*DIM
#define SCALEc 0.17677669529663689f   // 32^-0.5
#define NTOK (Bc*Lc)       // 36864

// ---------------- scratch (device globals; no allocation allowed) ----------
__device__ float g_xn   [NTOK * DIMc];     // LN output (reused for LN2)
__device__ float g_kv   [NTOK * 2 * DIMc]; // kv for all tokens (== kv_g, permuted == window kv)
__device__ float g_q    [NTOK * DIMc];
__device__ float g_x1   [NTOK * DIMc];     // x + attn residual
__device__ float g_h    [NTOK * HID];      // MLP hidden
__device__ float g_kvavg[Bc * 2 * DIMc];
__device__ float g_qavg [Bc * DIMc];
__device__ float g_xavgn[Bc * DIMc];
__device__ float g_xavg1[Bc * DIMc];
__device__ float g_havg [Bc * HID];

__device__ __forceinline__ float gelu_exact(float v) {
    return 0.5f * v * (1.0f + erff(v * 0.70710678118654752440f));
}

// ---------------- LayerNorm over DIM=512, one block per token --------------
__global__ __launch_bounds__(128)
void ln_kernel(const float* __restrict__ x, const float* __restrict__ g,
               const float* __restrict__ be, float* __restrict__ y)
{
    __shared__ float sS[4], sQ[4];
    const int t = blockIdx.x;
    const int tid = threadIdx.x;
    const float4 v = ((const float4*)(x + (size_t)t * DIMc))[tid];
    float s = v.x + v.y + v.z + v.w;
    float q = v.x*v.x + v.y*v.y + v.z*v.z + v.w*v.w;
    #pragma unroll
    for (int o = 16; o; o >>= 1) {
        s += __shfl_xor_sync(0xffffffffu, s, o);
        q += __shfl_xor_sync(0xffffffffu, q, o);
    }
    if ((tid & 31) == 0) { sS[tid >> 5] = s; sQ[tid >> 5] = q; }
    __syncthreads();
    const float S = sS[0] + sS[1] + sS[2] + sS[3];
    const float Q = sQ[0] + sQ[1] + sQ[2] + sQ[3];
    const float mean = S * (1.0f / 512.0f);
    const float var  = Q * (1.0f / 512.0f) - mean * mean;
    const float rstd = rsqrtf(var + 1e-3f);
    const float4 gg = ((const float4*)g)[tid];
    const float4 bb = ((const float4*)be)[tid];
    float4 o;
    o.x = (v.x - mean) * rstd * gg.x + bb.x;
    o.y = (v.y - mean) * rstd * gg.y + bb.y;
    o.z = (v.z - mean) * rstd * gg.z + bb.z;
    o.w = (v.w - mean) * rstd * gg.w + bb.w;
    ((float4*)(y + (size_t)t * DIMc))[tid] = o;
}

// ---------------- big SGEMM: C = act(A[MxK] @ W[KxN] + bias) (+R) ----------
// 128x128 block tile, 8x8 per thread, BK=8, 256 threads. All dims divisible.
template<int ACT, bool RES>
__global__ __launch_bounds__(256)
void sgemm(int M, int N, int K,
           const float* __restrict__ A, const float* __restrict__ W,
           const float* __restrict__ bias, const float* __restrict__ R,
           float* __restrict__ C)
{
    constexpr int BM = 128, BN = 128, BK = 8, TM = 8, TN = 8;
    __shared__ float As[BK][BM];
    __shared__ float Bs[BK][BN];
    const int tid  = threadIdx.x;
    const int bcol = blockIdx.x, brow = blockIdx.y;

    const int arow = tid >> 1;            // 0..127
    const int acol = (tid & 1) << 2;      // 0 or 4
    const int bro  = tid >> 5;            // 0..7
    const int bco  = (tid & 31) << 2;     // 0..124

    const int tr = (tid >> 4) * TM;
    const int tc = (tid & 15) * TN;

    const float* Aptr = A + (size_t)(brow * BM + arow) * K + acol;
    const float* Wptr = W + (size_t)bro * N + (size_t)bcol * BN + bco;

    float acc[TM][TN] = {};

    for (int k0 = 0; k0 < K; k0 += BK) {
        const float4 av = *(const float4*)(Aptr + k0);
        const float4 bv = *(const float4*)(Wptr + (size_t)k0 * N);
        As[acol + 0][arow] = av.x;
        As[acol + 1][arow] = av.y;
        As[acol + 2][arow] = av.z;
        As[acol + 3][arow] = av.w;
        *(float4*)&Bs[bro][bco] = bv;
        __syncthreads();
        #pragma unroll
        for (int k = 0; k < BK; k++) {
            float a[TM], b[TN];
            #pragma unroll
            for (int i = 0; i < TM; i += 4) *(float4*)&a[i] = *(const float4*)&As[k][tr + i];
            #pragma unroll
            for (int j = 0; j < TN; j += 4) *(float4*)&b[j] = *(const float4*)&Bs[k][tc + j];
            #pragma unroll
            for (int i = 0; i < TM; i++)
                #pragma unroll
                for (int j = 0; j < TN; j++)
                    acc[i][j] = fmaf(a[i], b[j], acc[i][j]);
        }
        __syncthreads();
    }

    #pragma unroll
    for (int i = 0; i < TM; i++) {
        const int r = brow * BM + tr + i;
        #pragma unroll
        for (int j = 0; j < TN; j += 4) {
            const int c = bcol * BN + tc + j;
            float4 v;
            v.x = acc[i][j+0] + bias[c+0];
            v.y = acc[i][j+1] + bias[c+1];
            v.z = acc[i][j+2] + bias[c+2];
            v.w = acc[i][j+3] + bias[c+3];
            if (ACT == 1) {
                v.x = gelu_exact(v.x); v.y = gelu_exact(v.y);
                v.z = gelu_exact(v.z); v.w = gelu_exact(v.w);
            }
            if (RES) {
                const float4 rr = *(const float4*)(R + (size_t)r * N + c);
                v.x += rr.x; v.y += rr.y; v.z += rr.z; v.w += rr.w;
            }
            *(float4*)(C + (size_t)r * N + c) = v;
        }
    }
}

// ---------------- tiny GEMM for the 16 global tokens -----------------------
template<int ACT, bool RES>
__global__ __launch_bounds__(128)
void small_gemm(int N, int K,
                const float* __restrict__ A, const float* __restrict__ W,
                const float* __restrict__ bias, const float* __restrict__ R,
                float* __restrict__ C)
{
    const int r = blockIdx.y;
    const int n = blockIdx.x * 128 + threadIdx.x;
    const float* a = A + (size_t)r * K;
    float acc = 0.0f;
    for (int k = 0; k < K; k++)
        acc = fmaf(__ldg(a + k), W[(size_t)k * N + n], acc);
    float v = acc + bias[n];
    if (ACT == 1) v = gelu_exact(v);
    if (RES) v += R[(size_t)r * N + n];
    C[(size_t)r * N + n] = v;
}

// ---------------- window attention: one block per (window, head) -----------
// 36 queries x 37 keys (36 window tokens + 1 global), HEAD=32. Gathers q/kv
// directly from the (B,L,*) layouts via the window permutation; writes
// x1 = x + attn_out scattered back to (B,L,DIM).
__global__ __launch_bounds__(128)
void win_attn(const float* __restrict__ q, const float* __restrict__ kv,
              const float* __restrict__ kvavg, const float* __restrict__ table,
              const float* __restrict__ xin, float* __restrict__ x1)
{
    const int w = blockIdx.x;            // 0..1023
    const int h = blockIdx.y;            // 0..15
    const int b  = w >> 6;
    const int wi = w & 63;
    const int wr = wi >> 3, wc = wi & 7;

    __shared__ float qs[36][33];
    __shared__ float ks[37][33];
    __shared__ float vs[37][33];
    __shared__ float sc[36][37];

    const int tid = threadIdx.x;

    for (int idx = tid; idx < 36 * 32; idx += 128) {
        const int m = idx >> 5, d = idx & 31;
        const int r = m / 6, c = m % 6;
        const int l = (wr * 6 + r) * 48 + wc * 6 + c;
        const size_t base = (size_t)(b * Lc + l);
        qs[m][d] = q[base * DIMc + h * 32 + d] * SCALEc;
        const float* kvp = kv + base * (2 * DIMc) + h * 32 + d;
        ks[m][d] = kvp[0];
        vs[m][d] = kvp[DIMc];
    }
    if (tid < 32) {
        ks[36][tid] = kvavg[(size_t)b * (2 * DIMc) + h * 32 + tid];
        vs[36][tid] = kvavg[(size_t)b * (2 * DIMc) + DIMc + h * 32 + tid];
    }
    __syncthreads();

    for (int p = tid; p < 36 * 37; p += 128) {
        const int mq = p / 37, mk = p % 37;
        float acc = 0.0f;
        #pragma unroll
        for (int d = 0; d < 32; d++) acc = fmaf(qs[mq][d], ks[mk][d], acc);
        int d0, d1;
        if (mk == 36) { d0 = mq % 6; d1 = mq / 6; }
        else          { d0 = mq % 6 - mk % 6; d1 = mq / 6 - mk / 6; }
        const int idx = (d0 + 5) * 11 + (d1 + 5);
        sc[mq][mk] = acc + table[idx * NHc + h];
    }
    __syncthreads();

    if (tid < 36) {
        float mx = -1e30f;
        #pragma unroll
        for (int k = 0; k < 37; k++) mx = fmaxf(mx, sc[tid][k]);
        float sum = 0.0f;
        #pragma unroll
        for (int k = 0; k < 37; k++) { const float e = expf(sc[tid][k] - mx); sc[tid][k] = e; sum += e; }
        const float inv = 1.0f / sum;
        #pragma unroll
        for (int k = 0; k < 37; k++) sc[tid][k] *= inv;
    }
    __syncthreads();

    for (int idx = tid; idx < 36 * 32; idx += 128) {
        const int m = idx >> 5, d = idx & 31;
        float acc = 0.0f;
        #pragma unroll
        for (int k = 0; k < 37; k++) acc = fmaf(sc[m][k], vs[k][d], acc);
        const int r = m / 6, c = m % 6;
        const int l = (wr * 6 + r) * 48 + wc * 6 + c;
        const size_t o = (size_t)(b * Lc + l) * DIMc + h * 32 + d;
        x1[o] = xin[o] + acc;
    }
}

// ---------------- global-token attention: one block per (b, h) -------------
__global__ __launch_bounds__(256)
void glob_attn(const float* __restrict__ qavg, const float* __restrict__ kv,
               const float* __restrict__ xavg_in, float* __restrict__ xavg1)
{
    const int b = blockIdx.x, h = blockIdx.y;
    __shared__ float qsh[32];
    __shared__ float wgt[Lc];
    __shared__ float red[8];
    const int tid = threadIdx.x, lane = tid & 31, wn = tid >> 5;

    if (tid < 32) qsh[tid] = qavg[(size_t)b * DIMc + h * 32 + tid] * SCALEc;
    __syncthreads();

    float lmax = -1e30f;
    for (int k = tid; k < Lc; k += 256) {
        const float4* kp = (const float4*)(kv + (size_t)(b * Lc + k) * (2 * DIMc) + h * 32);
        float acc = 0.0f;
        #pragma unroll
        for (int d4 = 0; d4 < 8; d4++) {
            const float4 kk = kp[d4];
            acc = fmaf(qsh[d4*4+0], kk.x, acc);
            acc = fmaf(qsh[d4*4+1], kk.y, acc);
            acc = fmaf(qsh[d4*4+2], kk.z, acc);
            acc = fmaf(qsh[d4*4+3], kk.w, acc);
        }
        wgt[k] = acc;
        lmax = fmaxf(lmax, acc);
    }
    #pragma unroll
    for (int o = 16; o; o >>= 1) lmax = fmaxf(lmax, __shfl_xor_sync(0xffffffffu, lmax, o));
    if (lane == 0) red[wn] = lmax;
    __syncthreads();
    float gmax = red[0];
    #pragma unroll
    for (int i = 1; i < 8; i++) gmax = fmaxf(gmax, red[i]);
    __syncthreads();

    float lsum = 0.0f;
    for (int k = tid; k < Lc; k += 256) {
        const float e = expf(wgt[k] - gmax);
        wgt[k] = e;
        lsum += e;
    }
    #pragma unroll
    for (int o = 16; o; o >>= 1) lsum += __shfl_xor_sync(0xffffffffu, lsum, o);
    if (lane == 0) red[wn] = lsum;
    __syncthreads();
    float gsum = 0.0f;
    #pragma unroll
    for (int i = 0; i < 8; i++) gsum += red[i];
    const float inv = 1.0f / gsum;

    // warp wn accumulates dims [wn*4, wn*4+4)
    float acc[4] = {0.f, 0.f, 0.f, 0.f};
    for (int k = lane; k < Lc; k += 32) {
        const float wk = wgt[k];
        const float4 vv = *(const float4*)(kv + (size_t)(b * Lc + k) * (2 * DIMc) + DIMc + h * 32 + wn * 4);
        acc[0] = fmaf(wk, vv.x, acc[0]);
        acc[1] = fmaf(wk, vv.y, acc[1]);
        acc[2] = fmaf(wk, vv.z, acc[2]);
        acc[3] = fmaf(wk, vv.w, acc[3]);
    }
    #pragma unroll
    for (int j = 0; j < 4; j++) {
        #pragma unroll
        for (int o = 16; o; o >>= 1) acc[j] += __shfl_xor_sync(0xffffffffu, acc[j], o);
    }
    if (lane == 0) {
        #pragma unroll
        for (int j = 0; j < 4; j++) {
            const size_t o = (size_t)b * DIMc + h * 32 + wn * 4 + j;
            xavg1[o] = xavg_in[o] + acc[j] * inv;
        }
    }
}

// ---------------------------------------------------------------------------
extern "C" void kernel_launch(void* const* d_in, const int* in_sizes, int n_in,
                              void* d_out, int out_size)
{
    const float* x     = (const float*)d_in[0];
    const float* xavg  = (const float*)d_in[1];
    const float* w_kv  = (const float*)d_in[2];
    const float* b_kv  = (const float*)d_in[3];
    const float* w_q   = (const float*)d_in[4];
    const float* b_q   = (const float*)d_in[5];
    const float* table = (const float*)d_in[6];
    const float* g1    = (const float*)d_in[7];
    const float* be1   = (const float*)d_in[8];
    const float* g2    = (const float*)d_in[9];
    const float* be2   = (const float*)d_in[10];
    const float* w_fc1 = (const float*)d_in[11];
    const float* b_fc1 = (const float*)d_in[12];
    const float* w_fc2 = (const float*)d_in[13];
    const float* b_fc2 = (const float*)d_in[14];
    float* out = (float*)d_out;

    float *xn, *kv, *q, *x1, *hbuf, *kvavg, *qavg, *xavgn, *xavg1, *havg;
    cudaGetSymbolAddress((void**)&xn,    g_xn);
    cudaGetSymbolAddress((void**)&kv,    g_kv);
    cudaGetSymbolAddress((void**)&q,     g_q);
    cudaGetSymbolAddress((void**)&x1,    g_x1);
    cudaGetSymbolAddress((void**)&hbuf,  g_h);
    cudaGetSymbolAddress((void**)&kvavg, g_kvavg);
    cudaGetSymbolAddress((void**)&qavg,  g_qavg);
    cudaGetSymbolAddress((void**)&xavgn, g_xavgn);
    cudaGetSymbolAddress((void**)&xavg1, g_xavg1);
    cudaGetSymbolAddress((void**)&havg,  g_havg);

    // 1. LayerNorm 1
    ln_kernel<<<NTOK, 128>>>(x,    g1, be1, xn);
    ln_kernel<<<Bc,   128>>>(xavg, g1, be1, xavgn);

    // 2. Projections (kv computed once for all tokens; window kv == permutation)
    sgemm<0, false><<<dim3(1024/128, NTOK/128), 256>>>(NTOK, 2*DIMc, DIMc, xn, w_kv, b_kv, nullptr, kv);
    sgemm<0, false><<<dim3( 512/128, NTOK/128), 256>>>(NTOK,   DIMc, DIMc, xn, w_q,  b_q,  nullptr, q);
    small_gemm<0, false><<<dim3(1024/128, Bc), 128>>>(2*DIMc, DIMc, xavgn, w_kv, b_kv, nullptr, kvavg);
    small_gemm<0, false><<<dim3( 512/128, Bc), 128>>>(  DIMc, DIMc, xavgn, w_q,  b_q,  nullptr, qavg);

    // 3. Attention (+ residual)
    win_attn <<<dim3(Bc*NWc, NHc), 128>>>(q, kv, kvavg, table, x, x1);
    glob_attn<<<dim3(Bc,     NHc), 256>>>(qavg, kv, xavg, xavg1);

    // 4. LayerNorm 2
    ln_kernel<<<NTOK, 128>>>(x1,    g2, be2, xn);
    ln_kernel<<<Bc,   128>>>(xavg1, g2, be2, xavgn);

    // 5. MLP (+ residual), writing final outputs
    sgemm<1, false><<<dim3(HID/128, NTOK/128), 256>>>(NTOK, HID,  DIMc, xn,   w_fc1, b_fc1, nullptr, hbuf);
    sgemm<0, true ><<<dim3(DIMc/128, NTOK/128), 256>>>(NTOK, DIMc, HID,  hbuf, w_fc2, b_fc2, x1, out);
    small_gemm<1, false><<<dim3(HID/128,  Bc), 128>>>(HID,  DIMc, xavgn, w_fc1, b_fc1, nullptr, havg);
    small_gemm<0, true ><<<dim3(DIMc/128, Bc), 128>>>(DIMc, HID,  havg,  w_fc2, b_fc2, xavg1, out + (size_t)NTOK * DIMc);
}

// round 2
// speedup vs baseline: 2.5127x; 2.5127x over previous
#include <cuda_runtime.h>
#include <math.h>
#include <stdint.h>

// Problem constants
#define Bc   16
#define NHc  16
#define DIMc 512
#define Lc   2304          // 48*48
#define NWc  64            // (48/6)^2
#define HID  2048          // 4*DIM
#define SCALEc 0.17677669529663689f   // 32^-0.5
#define NTOK (Bc*Lc)       // 36864

// ---------------- scratch (device globals; no allocation allowed) ----------
__device__ float g_xn   [NTOK * DIMc];
__device__ float g_kv   [NTOK * 2 * DIMc];
__device__ float g_q    [NTOK * DIMc];
__device__ float g_x1   [NTOK * DIMc];
__device__ float g_h    [NTOK * HID];
__device__ float g_kvavg[Bc * 2 * DIMc];
__device__ float g_qavg [Bc * DIMc];
__device__ float g_xavgn[Bc * DIMc];
__device__ float g_xavg1[Bc * DIMc];
__device__ float g_havg [Bc * HID];

__device__ __forceinline__ float gelu_exact(float v) {
    return 0.5f * v * (1.0f + erff(v * 0.70710678118654752440f));
}

__device__ __forceinline__ uint32_t cvt_tf32(float f) {
    uint32_t u;
    asm("cvt.rna.tf32.f32 %0, %1;" : "=r"(u) : "f"(f));
    return u;
}

#define CP16(dst, src) \
    asm volatile("cp.async.cg.shared.global [%0], [%1], 16;\n" :: "r"(dst), "l"(src))
#define CPCOMMIT() asm volatile("cp.async.commit_group;\n")

// ---------------- LayerNorm over DIM=512, one block per token --------------
__global__ __launch_bounds__(128)
void ln_kernel(const float* __restrict__ x, const float* __restrict__ g,
               const float* __restrict__ be, float* __restrict__ y)
{
    __shared__ float sS[4], sQ[4];
    const int t = blockIdx.x;
    const int tid = threadIdx.x;
    const float4 v = ((const float4*)(x + (size_t)t * DIMc))[tid];
    float s = v.x + v.y + v.z + v.w;
    float q = v.x*v.x + v.y*v.y + v.z*v.z + v.w*v.w;
    #pragma unroll
    for (int o = 16; o; o >>= 1) {
        s += __shfl_xor_sync(0xffffffffu, s, o);
        q += __shfl_xor_sync(0xffffffffu, q, o);
    }
    if ((tid & 31) == 0) { sS[tid >> 5] = s; sQ[tid >> 5] = q; }
    __syncthreads();
    const float S = sS[0] + sS[1] + sS[2] + sS[3];
    const float Q = sQ[0] + sQ[1] + sQ[2] + sQ[3];
    const float mean = S * (1.0f / 512.0f);
    const float var  = Q * (1.0f / 512.0f) - mean * mean;
    const float rstd = rsqrtf(var + 1e-3f);
    const float4 gg = ((const float4*)g)[tid];
    const float4 bb = ((const float4*)be)[tid];
    float4 o;
    o.x = (v.x - mean) * rstd * gg.x + bb.x;
    o.y = (v.y - mean) * rstd * gg.y + bb.y;
    o.z = (v.z - mean) * rstd * gg.z + bb.z;
    o.w = (v.w - mean) * rstd * gg.w + bb.w;
    ((float4*)(y + (size_t)t * DIMc))[tid] = o;
}

// ---------------- tf32 tensor-core GEMM ------------------------------------
// C[MxN] = act(A[MxK] @ W[KxN] + bias) (+R). 128x128x16 tile, 256 threads,
// 2x4 warp grid (64x32 per warp), mma.sync.m16n8k8.tf32, double-buffered
// cp.async loads. All dims divisible by tile sizes.
template<int ACT, bool RES>
__global__ __launch_bounds__(256, 2)
void tgemm(int M, int N, int K,
           const float* __restrict__ A, const float* __restrict__ W,
           const float* __restrict__ bias, const float* __restrict__ R,
           float* __restrict__ C)
{
    constexpr int BM = 128, BN = 128, BK = 16;
    constexpr int APAD = 20;   // floats per A row in smem (conflict-free frag loads)
    constexpr int BPAD = 132;  // floats per B row in smem

    __shared__ float As[2][BM * APAD];
    __shared__ float Bs[2][BK * BPAD];

    const int tid  = threadIdx.x;
    const int lane = tid & 31;
    const int warp = tid >> 5;
    const int wm   = warp >> 2;          // 0..1
    const int wn   = warp & 3;           // 0..3
    const int bm   = blockIdx.y * BM;
    const int bn   = blockIdx.x * BN;

    // ---- async-copy thread mapping ----
    // A tile: 128 rows x 16 cols = 512 x 16B chunks; 2 per thread
    const int a_r = tid >> 2;                 // 0..63
    const int a_p = (tid & 3) << 2;           // 0,4,8,12
    const float* a_src0 = A + (size_t)(bm + a_r) * K + a_p;
    const float* a_src1 = a_src0 + (size_t)64 * K;
    // B tile: 16 rows x 128 cols = 512 x 16B chunks; 2 per thread
    const int b_r = tid >> 5;                 // 0..7
    const int b_c = (lane) << 2;              // 0..124
    const float* b_src0 = W + (size_t)b_r * N + bn + b_c;
    const float* b_src1 = b_src0 + (size_t)8 * N;

    const uint32_t sA0 = (uint32_t)__cvta_generic_to_shared(&As[0][0]);
    const uint32_t sB0 = (uint32_t)__cvta_generic_to_shared(&Bs[0][0]);
    const uint32_t a_dst0 = sA0 + (uint32_t)(a_r * APAD + a_p) * 4u;
    const uint32_t a_dst1 = a_dst0 + (uint32_t)(64 * APAD) * 4u;
    const uint32_t b_dst0 = sB0 + (uint32_t)(b_r * BPAD + b_c) * 4u;
    const uint32_t b_dst1 = b_dst0 + (uint32_t)(8 * BPAD) * 4u;
    const uint32_t aBufStride = (uint32_t)(BM * APAD) * 4u;
    const uint32_t bBufStride = (uint32_t)(BK * BPAD) * 4u;

    float acc[4][4][4] = {};   // [mt][nt][4]

    const int T = K / BK;

    // prologue: stage 0
    CP16(a_dst0, a_src0);
    CP16(a_dst1, a_src1);
    CP16(b_dst0, b_src0);
    CP16(b_dst1, b_src1);
    CPCOMMIT();

    int buf = 0;
    for (int t = 0; t < T; t++) {
        if (t + 1 < T) {
            const int k0 = (t + 1) * BK;
            const uint32_t ao = (buf ^ 1) * aBufStride;
            const uint32_t bo = (buf ^ 1) * bBufStride;
            CP16(a_dst0 + ao, a_src0 + k0);
            CP16(a_dst1 + ao, a_src1 + k0);
            CP16(b_dst0 + bo, b_src0 + (size_t)k0 * N);
            CP16(b_dst1 + bo, b_src1 + (size_t)k0 * N);
            CPCOMMIT();
            asm volatile("cp.async.wait_group 1;\n");
        } else {
            asm volatile("cp.async.wait_group 0;\n");
        }
        __syncthreads();

        const float* As_ = &As[buf][0];
        const float* Bs_ = &Bs[buf][0];
        const int ar = wm * 64 + (lane >> 2);
        const int ac = lane & 3;
        const int bc = wn * 32 + (lane >> 2);
        const int br = lane & 3;

        #pragma unroll
        for (int ks = 0; ks < BK; ks += 8) {
            uint32_t af[4][4];
            #pragma unroll
            for (int mt = 0; mt < 4; mt++) {
                const float* p = As_ + (ar + mt * 16) * APAD + ks + ac;
                af[mt][0] = cvt_tf32(p[0]);
                af[mt][1] = cvt_tf32(p[8 * APAD]);
                af[mt][2] = cvt_tf32(p[4]);
                af[mt][3] = cvt_tf32(p[8 * APAD + 4]);
            }
            uint32_t bf[4][2];
            #pragma unroll
            for (int nt = 0; nt < 4; nt++) {
                const float* p = Bs_ + (ks + br) * BPAD + bc + nt * 8;
                bf[nt][0] = cvt_tf32(p[0]);
                bf[nt][1] = cvt_tf32(p[4 * BPAD]);
            }
            #pragma unroll
            for (int mt = 0; mt < 4; mt++)
                #pragma unroll
                for (int nt = 0; nt < 4; nt++)
                    asm volatile(
                        "mma.sync.aligned.m16n8k8.row.col.f32.tf32.tf32.f32 "
                        "{%0,%1,%2,%3}, {%4,%5,%6,%7}, {%8,%9}, {%0,%1,%2,%3};\n"
                        : "+f"(acc[mt][nt][0]), "+f"(acc[mt][nt][1]),
                          "+f"(acc[mt][nt][2]), "+f"(acc[mt][nt][3])
                        : "r"(af[mt][0]), "r"(af[mt][1]), "r"(af[mt][2]), "r"(af[mt][3]),
                          "r"(bf[nt][0]), "r"(bf[nt][1]));
        }
        __syncthreads();
        buf ^= 1;
    }

    // ---- epilogue ----
    #pragma unroll
    for (int mt = 0; mt < 4; mt++) {
        #pragma unroll
        for (int nt = 0; nt < 4; nt++) {
            const int r0 = bm + wm * 64 + mt * 16 + (lane >> 2);
            const int c  = bn + wn * 32 + nt * 8 + (lane & 3) * 2;
            const float bx = bias[c], by = bias[c + 1];
            #pragma unroll
            for (int half = 0; half < 2; half++) {
                const int r = r0 + half * 8;
                float vx = acc[mt][nt][half * 2 + 0] + bx;
                float vy = acc[mt][nt][half * 2 + 1] + by;
                if (ACT == 1) { vx = gelu_exact(vx); vy = gelu_exact(vy); }
                if (RES) {
                    const float2 rr = *(const float2*)(R + (size_t)r * N + c);
                    vx += rr.x; vy += rr.y;
                }
                float2 o; o.x = vx; o.y = vy;
                *(float2*)(C + (size_t)r * N + c) = o;
            }
        }
    }
}

// ---------------- tiny GEMM for the 16 global tokens -----------------------
template<int ACT, bool RES>
__global__ __launch_bounds__(128)
void small_gemm(int N, int K,
                const float* __restrict__ A, const float* __restrict__ W,
                const float* __restrict__ bias, const float* __restrict__ R,
                float* __restrict__ C)
{
    const int r = blockIdx.y;
    const int n = blockIdx.x * 128 + threadIdx.x;
    const float* a = A + (size_t)r * K;
    float acc = 0.0f;
    for (int k = 0; k < K; k++)
        acc = fmaf(__ldg(a + k), W[(size_t)k * N + n], acc);
    float v = acc + bias[n];
    if (ACT == 1) v = gelu_exact(v);
    if (RES) v += R[(size_t)r * N + n];
    C[(size_t)r * N + n] = v;
}

// ---------------- window attention: one block per (window, head) -----------
__global__ __launch_bounds__(128)
void win_attn(const float* __restrict__ q, const float* __restrict__ kv,
              const float* __restrict__ kvavg, const float* __restrict__ table,
              const float* __restrict__ xin, float* __restrict__ x1)
{
    const int w = blockIdx.x;            // 0..1023
    const int h = blockIdx.y;            // 0..15
    const int b  = w >> 6;
    const int wi = w & 63;
    const int wr = wi >> 3, wc = wi & 7;

    __shared__ float qs[36][33];
    __shared__ float ks[37][33];
    __shared__ float vs[37][33];
    __shared__ float sc[36][37];

    const int tid = threadIdx.x;

    for (int idx = tid; idx < 36 * 32; idx += 128) {
        const int m = idx >> 5, d = idx & 31;
        const int r = m / 6, c = m % 6;
        const int l = (wr * 6 + r) * 48 + wc * 6 + c;
        const size_t base = (size_t)(b * Lc + l);
        qs[m][d] = q[base * DIMc + h * 32 + d] * SCALEc;
        const float* kvp = kv + base * (2 * DIMc) + h * 32 + d;
        ks[m][d] = kvp[0];
        vs[m][d] = kvp[DIMc];
    }
    if (tid < 32) {
        ks[36][tid] = kvavg[(size_t)b * (2 * DIMc) + h * 32 + tid];
        vs[36][tid] = kvavg[(size_t)b * (2 * DIMc) + DIMc + h * 32 + tid];
    }
    __syncthreads();

    for (int p = tid; p < 36 * 37; p += 128) {
        const int mq = p / 37, mk = p % 37;
        float acc = 0.0f;
        #pragma unroll
        for (int d = 0; d < 32; d++) acc = fmaf(qs[mq][d], ks[mk][d], acc);
        int d0, d1;
        if (mk == 36) { d0 = mq % 6; d1 = mq / 6; }
        else          { d0 = mq % 6 - mk % 6; d1 = mq / 6 - mk / 6; }
        const int idx = (d0 + 5) * 11 + (d1 + 5);
        sc[mq][mk] = acc + table[idx * NHc + h];
    }
    __syncthreads();

    if (tid < 36) {
        float mx = -1e30f;
        #pragma unroll
        for (int k = 0; k < 37; k++) mx = fmaxf(mx, sc[tid][k]);
        float sum = 0.0f;
        #pragma unroll
        for (int k = 0; k < 37; k++) { const float e = expf(sc[tid][k] - mx); sc[tid][k] = e; sum += e; }
        const float inv = 1.0f / sum;
        #pragma unroll
        for (int k = 0; k < 37; k++) sc[tid][k] *= inv;
    }
    __syncthreads();

    for (int idx = tid; idx < 36 * 32; idx += 128) {
        const int m = idx >> 5, d = idx & 31;
        float acc = 0.0f;
        #pragma unroll
        for (int k = 0; k < 37; k++) acc = fmaf(sc[m][k], vs[k][d], acc);
        const int r = m / 6, c = m % 6;
        const int l = (wr * 6 + r) * 48 + wc * 6 + c;
        const size_t o = (size_t)(b * Lc + l) * DIMc + h * 32 + d;
        x1[o] = xin[o] + acc;
    }
}

// ---------------- global-token attention: one block per (b, h) -------------
__global__ __launch_bounds__(256)
void glob_attn(const float* __restrict__ qavg, const float* __restrict__ kv,
               const float* __restrict__ xavg_in, float* __restrict__ xavg1)
{
    const int b = blockIdx.x, h = blockIdx.y;
    __shared__ float qsh[32];
    __shared__ float wgt[Lc];
    __shared__ float red[8];
    const int tid = threadIdx.x, lane = tid & 31, wn = tid >> 5;

    if (tid < 32) qsh[tid] = qavg[(size_t)b * DIMc + h * 32 + tid] * SCALEc;
    __syncthreads();

    float lmax = -1e30f;
    for (int k = tid; k < Lc; k += 256) {
        const float4* kp = (const float4*)(kv + (size_t)(b * Lc + k) * (2 * DIMc) + h * 32);
        float acc = 0.0f;
        #pragma unroll
        for (int d4 = 0; d4 < 8; d4++) {
            const float4 kk = kp[d4];
            acc = fmaf(qsh[d4*4+0], kk.x, acc);
            acc = fmaf(qsh[d4*4+1], kk.y, acc);
            acc = fmaf(qsh[d4*4+2], kk.z, acc);
            acc = fmaf(qsh[d4*4+3], kk.w, acc);
        }
        wgt[k] = acc;
        lmax = fmaxf(lmax, acc);
    }
    #pragma unroll
    for (int o = 16; o; o >>= 1) lmax = fmaxf(lmax, __shfl_xor_sync(0xffffffffu, lmax, o));
    if (lane == 0) red[wn] = lmax;
    __syncthreads();
    float gmax = red[0];
    #pragma unroll
    for (int i = 1; i < 8; i++) gmax = fmaxf(gmax, red[i]);
    __syncthreads();

    float lsum = 0.0f;
    for (int k = tid; k < Lc; k += 256) {
        const float e = expf(wgt[k] - gmax);
        wgt[k] = e;
        lsum += e;
    }
    #pragma unroll
    for (int o = 16; o; o >>= 1) lsum += __shfl_xor_sync(0xffffffffu, lsum, o);
    if (lane == 0) red[wn] = lsum;
    __syncthreads();
    float gsum = 0.0f;
    #pragma unroll
    for (int i = 0; i < 8; i++) gsum += red[i];
    const float inv = 1.0f / gsum;

    float acc[4] = {0.f, 0.f, 0.f, 0.f};
    for (int k = lane; k < Lc; k += 32) {
        const float wk = wgt[k];
        const float4 vv = *(const float4*)(kv + (size_t)(b * Lc + k) * (2 * DIMc) + DIMc + h * 32 + wn * 4);
        acc[0] = fmaf(wk, vv.x, acc[0]);
        acc[1] = fmaf(wk, vv.y, acc[1]);
        acc[2] = fmaf(wk, vv.z, acc[2]);
        acc[3] = fmaf(wk, vv.w, acc[3]);
    }
    #pragma unroll
    for (int j = 0; j < 4; j++) {
        #pragma unroll
        for (int o = 16; o; o >>= 1) acc[j] += __shfl_xor_sync(0xffffffffu, acc[j], o);
    }
    if (lane == 0) {
        #pragma unroll
        for (int j = 0; j < 4; j++) {
            const size_t o = (size_t)b * DIMc + h * 32 + wn * 4 + j;
            xavg1[o] = xavg_in[o] + acc[j] * inv;
        }
    }
}

// ---------------------------------------------------------------------------
extern "C" void kernel_launch(void* const* d_in, const int* in_sizes, int n_in,
                              void* d_out, int out_size)
{
    const float* x     = (const float*)d_in[0];
    const float* xavg  = (const float*)d_in[1];
    const float* w_kv  = (const float*)d_in[2];
    const float* b_kv  = (const float*)d_in[3];
    const float* w_q   = (const float*)d_in[4];
    const float* b_q   = (const float*)d_in[5];
    const float* table = (const float*)d_in[6];
    const float* g1    = (const float*)d_in[7];
    const float* be1   = (const float*)d_in[8];
    const float* g2    = (const float*)d_in[9];
    const float* be2   = (const float*)d_in[10];
    const float* w_fc1 = (const float*)d_in[11];
    const float* b_fc1 = (const float*)d_in[12];
    const float* w_fc2 = (const float*)d_in[13];
    const float* b_fc2 = (const float*)d_in[14];
    float* out = (float*)d_out;

    float *xn, *kv, *q, *x1, *hbuf, *kvavg, *qavg, *xavgn, *xavg1, *havg;
    cudaGetSymbolAddress((void**)&xn,    g_xn);
    cudaGetSymbolAddress((void**)&kv,    g_kv);
    cudaGetSymbolAddress((void**)&q,     g_q);
    cudaGetSymbolAddress((void**)&x1,    g_x1);
    cudaGetSymbolAddress((void**)&hbuf,  g_h);
    cudaGetSymbolAddress((void**)&kvavg, g_kvavg);
    cudaGetSymbolAddress((void**)&qavg,  g_qavg);
    cudaGetSymbolAddress((void**)&xavgn, g_xavgn);
    cudaGetSymbolAddress((void**)&xavg1, g_xavg1);
    cudaGetSymbolAddress((void**)&havg,  g_havg);

    // 1. LayerNorm 1
    ln_kernel<<<NTOK, 128>>>(x,    g1, be1, xn);
    ln_kernel<<<Bc,   128>>>(xavg, g1, be1, xavgn);

    // 2. Projections (kv computed once for all tokens; window kv == permutation)
    tgemm<0, false><<<dim3(1024/128, NTOK/128), 256>>>(NTOK, 2*DIMc, DIMc, xn, w_kv, b_kv, nullptr, kv);
    tgemm<0, false><<<dim3( 512/128, NTOK/128), 256>>>(NTOK,   DIMc, DIMc, xn, w_q,  b_q,  nullptr, q);
    small_gemm<0, false><<<dim3(1024/128, Bc), 128>>>(2*DIMc, DIMc, xavgn, w_kv, b_kv, nullptr, kvavg);
    small_gemm<0, false><<<dim3( 512/128, Bc), 128>>>(  DIMc, DIMc, xavgn, w_q,  b_q,  nullptr, qavg);

    // 3. Attention (+ residual)
    win_attn <<<dim3(Bc*NWc, NHc), 128>>>(q, kv, kvavg, table, x, x1);
    glob_attn<<<dim3(Bc,     NHc), 256>>>(qavg, kv, xavg, xavg1);

    // 4. LayerNorm 2
    ln_kernel<<<NTOK, 128>>>(x1,    g2, be2, xn);
    ln_kernel<<<Bc,   128>>>(xavg1, g2, be2, xavgn);

    // 5. MLP (+ residual), writing final outputs
    tgemm<1, false><<<dim3(HID/128, NTOK/128), 256>>>(NTOK, HID,  DIMc, xn,   w_fc1, b_fc1, nullptr, hbuf);
    tgemm<0, true ><<<dim3(DIMc/128, NTOK/128), 256>>>(NTOK, DIMc, HID,  hbuf, w_fc2, b_fc2, x1, out);
    small_gemm<1, false><<<dim3(HID/128,  Bc), 128>>>(HID,  DIMc, xavgn, w_fc1, b_fc1, nullptr, havg);
    small_gemm<0, true ><<<dim3(DIMc/128, Bc), 128>>>(DIMc, HID,  havg,  w_fc2, b_fc2, xavg1, out + (size_t)NTOK * DIMc);
}